// round 14
// baseline (speedup 1.0000x reference)
#include <cuda_runtime.h>
#include <math.h>

#define BATCH 2
#define CC 256
#define NN 4096
#define HEADS 32
#define HD 8
#define KTOP 512
#define CN (CC*NN)

typedef unsigned long long u64;

// ---- packed f32x2 helpers ----
__device__ __forceinline__ u64 pack2(float lo, float hi) {
    u64 r; asm("mov.b64 %0, {%1, %2};" : "=l"(r) : "f"(lo), "f"(hi)); return r;
}
__device__ __forceinline__ u64 dup2(float a) {
    u64 r; asm("mov.b64 %0, {%1, %1};" : "=l"(r) : "f"(a)); return r;
}
__device__ __forceinline__ void unpack2(u64 p, float& lo, float& hi) {
    asm("mov.b64 {%0, %1}, %2;" : "=f"(lo), "=f"(hi) : "l"(p));
}
__device__ __forceinline__ u64 ffma2(u64 a, u64 b, u64 c) {
    u64 d; asm("fma.rn.f32x2 %0, %1, %2, %3;" : "=l"(d) : "l"(a), "l"(b), "l"(c)); return d;
}
__device__ __forceinline__ u64 mul2(u64 a, u64 b) {
    u64 d; asm("mul.rn.f32x2 %0, %1, %2;" : "=l"(d) : "l"(a), "l"(b)); return d;
}
__device__ __forceinline__ float ex2f(float x) {
    float r; asm("ex2.approx.f32 %0, %1;" : "=f"(r) : "f"(x)); return r;
}

// ---------------- scratch (device globals; no allocation) ----------------
__device__ float g_avgmax[BATCH*2*NN];
__device__ float g_scores[BATCH*NN];
__device__ int   g_idx[BATCH*KTOP];
__device__ int   g_tflag[BATCH];           // 0 -> topk pending; 1 -> idx ready
__device__ float g_q[BATCH*NN*CC];
__device__ float g_kvg[BATCH*KTOP*2*CC];   // [b][k][0:256]=K, [256:512]=V
__device__ float g_vvol[BATCH*CN];
__device__ float g_cat[BATCH*2*CN];        // [b][0:256]=attn_t, [256:512]=dw  (C,N)
__device__ float g_wcat[2*CC*CC];          // [k][c]: k<256 w_proj, k>=256 w_pw^T
__device__ float g_bcat[CC];               // b_proj + b_pw

// ---------------- 1. channel avg/max reduce (4-way c-split) ----------------
__global__ void k_reduce(const float* __restrict__ x) {
    __shared__ float ssum[4][64], smax[4][64];
    int b = blockIdx.y;
    int n0 = blockIdx.x * 64;
    int cq = threadIdx.x >> 6;
    int nn = threadIdx.x & 63;
    const float* p = x + (long)b*CN + n0 + nn;
    float s = 0.f, mx = -INFINITY;
#pragma unroll 8
    for (int c = cq*64; c < cq*64 + 64; c++) {
        float v = p[(long)c*NN]; s += v; mx = fmaxf(mx, v);
    }
    ssum[cq][nn] = s; smax[cq][nn] = mx;
    __syncthreads();
    if (cq == 0) {
        s = ssum[0][nn] + ssum[1][nn] + ssum[2][nn] + ssum[3][nn];
        mx = fmaxf(fmaxf(smax[0][nn], smax[1][nn]), fmaxf(smax[2][nn], smax[3][nn]));
        g_avgmax[(b*2+0)*NN + n0 + nn] = s * (1.0f/CC);
        g_avgmax[(b*2+1)*NN + n0 + nn] = mx;
    }
}

// ---------------- 2. 7x7x7 spatial conv (2ch -> 1ch) + sigmoid ----------------
__global__ void k_spa(const float* __restrict__ w_spa) {
    __shared__ float w[686];
    int tid = threadIdx.x;
    for (int l = tid; l < 686; l += blockDim.x) w[l] = w_spa[l];
    __syncthreads();
    int i = blockIdx.x * blockDim.x + tid;
    if (i >= BATCH*NN) return;
    int b = i >> 12, n = i & (NN-1);
    int z = n >> 8, y = (n >> 4) & 15, x0 = n & 15;
    float s = 0.f;
    for (int ci = 0; ci < 2; ci++) {
        const float* in = g_avgmax + (b*2+ci)*NN;
        const float* wc = w + ci*343;
        for (int dz = 0; dz < 7; dz++) {
            int zz = z + dz - 3; if (zz < 0 || zz > 15) continue;
            for (int dy = 0; dy < 7; dy++) {
                int yy = y + dy - 3; if (yy < 0 || yy > 15) continue;
                const float* row = in + zz*256 + yy*16;
                const float* wr = wc + dz*49 + dy*7;
                for (int dx = 0; dx < 7; dx++) {
                    int xx = x0 + dx - 3; if (xx < 0 || xx > 15) continue;
                    s += wr[dx] * row[xx];
                }
            }
        }
    }
    g_scores[i] = 1.0f / (1.0f + __expf(-s));
}

// ---------------- GemmOp ----------------
struct GemmOp {
    const float* A; long a_ms, a_ks, a_bs;
    const int* rowidx; long ridx_bs;
    const float* Bw; int ldb; long w_bs;
    const float* bias_j; const float* bias_m; const float* addend;
    float* C; long c_ms, c_js, c_bs;
    int K; int tx; int ty;
};

// ---------------- topk role (256 threads): radix select, sets g_tflag --------
__device__ void topk_role(int b, char* sraw) {
    unsigned* skey = (unsigned*)sraw;                   // 16384 B
    unsigned* hist = (unsigned*)(sraw + 16384);         // 1024 B
    unsigned* scan = (unsigned*)(sraw + 17408);         // 1024 B
    unsigned* S    = (unsigned*)(sraw + 18432);         // sel,need,neednxt,cnt,tie
    int tid = threadIdx.x;
    const unsigned* keys = (const unsigned*)g_scores + b*NN;
    for (int i = tid; i < NN; i += 256) skey[i] = keys[i];
    if (tid == 0) S[1] = KTOP;
    __syncthreads();
    unsigned prefix = 0, pmask = 0;
    for (int shift = 24; shift >= 0; shift -= 8) {
        hist[tid] = 0;
        __syncthreads();
        for (int i = tid; i < NN; i += 256) {
            unsigned k = skey[i];
            if ((k & pmask) == prefix) atomicAdd(&hist[(k >> shift) & 255u], 1u);
        }
        __syncthreads();
        scan[tid] = hist[255 - tid];
        __syncthreads();
#pragma unroll
        for (int off = 1; off < 256; off <<= 1) {
            unsigned add = (tid >= off) ? scan[tid - off] : 0u;
            __syncthreads();
            scan[tid] += add;
            __syncthreads();
        }
        unsigned need = S[1];
        unsigned suf = scan[tid], above = tid ? scan[tid - 1] : 0u;
        if (suf >= need && above < need) { S[0] = 255u - tid; S[2] = need - above; }
        __syncthreads();
        prefix |= S[0] << shift;
        pmask  |= 255u << shift;
        if (tid == 0) S[1] = S[2];
        __syncthreads();
    }
    if (tid == 0) { S[3] = 0; S[4] = 0; }
    __syncthreads();
    unsigned tietake = S[1];
    for (int i = tid; i < NN; i += 256) {
        unsigned k = skey[i];
        if (k > prefix) {
            unsigned p = atomicAdd(&S[3], 1u);
            g_idx[b*KTOP + p] = i;
        } else if (k == prefix) {
            unsigned t = atomicAdd(&S[4], 1u);
            if (t < tietake) {
                unsigned p = atomicAdd(&S[3], 1u);
                g_idx[b*KTOP + p] = i;
            }
        }
    }
    __threadfence();
    __syncthreads();
    if (tid == 0) atomicExch(&g_tflag[b], 1);
}

// ---------------- mega kernel: topk(2) + QVK gemms(288) + wcat prep(128) -----
__global__ void __launch_bounds__(256) k_mega(
    GemmOp o1, GemmOp o2, GemmOp o3,
    const float* __restrict__ w_proj, const float* __restrict__ w_pw,
    const float* __restrict__ b_proj, const float* __restrict__ b_pw)
{
    __shared__ __align__(16) char sraw[34816];
    int bid = blockIdx.x;
    int tid = threadIdx.x;

    if (bid < 2) { topk_role(bid, sraw); return; }
    bid -= 2;
    if (bid >= 288) {                       // prep role: 128 blocks x 1024 elems
        int e0 = (bid - 288) * 1024 + tid * 4;
#pragma unroll
        for (int j = 0; j < 4; j++) {
            int e = e0 + j;
            int k = e >> 8, c = e & 255;
            g_wcat[e] = (k < CC) ? w_proj[k*CC + c] : w_pw[c*CC + (k - CC)];
            if (e < CC) g_bcat[e] = b_proj[e] + b_pw[e];
        }
        return;
    }

    // ---- GEMM role ----
    float (&As)[2][16][132] = *reinterpret_cast<float(*)[2][16][132]>(sraw);
    float (&Bs)[2][16][132] = *reinterpret_cast<float(*)[2][16][132]>(sraw + 16896);
    int*  sidx = (int*)(sraw + 33792);

    GemmOp op; int local;
    if (bid < 128)      { op = o1; local = bid; }
    else if (bid < 256) { op = o2; local = bid - 128; }
    else                { op = o3; local = bid - 256; }
    int per = op.tx * op.ty;
    int bz  = local / per;
    int rem = local - bz * per;
    int m0 = (rem / op.tx) * 128, j0 = (rem % op.tx) * 128;

    const float* Ab = op.A  + (long)bz * op.a_bs;
    const float* Bb = op.Bw + (long)bz * op.w_bs;

    int mode = op.rowidx ? 2 : ((op.a_ks == 1) ? 0 : 1);

    int warp = tid >> 5, lane = tid & 31;
    int tm = (warp & 3) * 32 + (lane & 3) * 8;
    int tn = (warp >> 2) * 64 + (lane >> 2) * 8;

    int am  = tid >> 1, ak = (tid & 1) * 8;     // mode 0
    int am4 = (tid & 31) * 4, ak2 = tid >> 5;   // mode 1
    int bj4 = (tid & 31) * 4, bk  = tid >> 5;   // B

    long goff[8]; int gmm[8], gkk[8];
    if (mode == 2) {
        // wait for topk blocks (lowest bids, resident first) to publish g_idx
        if (tid == 0) { while (atomicAdd(&g_tflag[bz], 0) == 0) {} }
        __syncthreads();
        if (tid < 128) sidx[tid] = op.rowidx[(long)bz * op.ridx_bs + m0 + tid];
        __syncthreads();
#pragma unroll
        for (int r = 0; r < 8; r++) {
            int l = tid + r * 256;
            gmm[r] = l & 127; gkk[r] = l >> 7;
            goff[r] = (long)gkk[r] * op.a_ks + sidx[gmm[r]];
        }
    }

    const float* pA = Ab;
    if (mode == 0)      pA = Ab + (long)(m0 + am) * op.a_ms + ak;
    else if (mode == 1) pA = Ab + (long)ak2 * op.a_ks + m0 + am4;
    const float* pB = Bb + (long)bk * op.ldb + j0 + bj4;

    float fa[8]; float4 fb0, fb1;
    auto fetch = [&](int t) {
        long k0 = (long)t * 16;
        if (mode == 0) {
            float4 v0 = *(const float4*)(pA + k0);
            float4 v1 = *(const float4*)(pA + k0 + 4);
            fa[0]=v0.x; fa[1]=v0.y; fa[2]=v0.z; fa[3]=v0.w;
            fa[4]=v1.x; fa[5]=v1.y; fa[6]=v1.z; fa[7]=v1.w;
        } else if (mode == 1) {
            float4 v0 = *(const float4*)(pA + k0 * op.a_ks);
            float4 v1 = *(const float4*)(pA + (k0 + 8) * op.a_ks);
            fa[0]=v0.x; fa[1]=v0.y; fa[2]=v0.z; fa[3]=v0.w;
            fa[4]=v1.x; fa[5]=v1.y; fa[6]=v1.z; fa[7]=v1.w;
        } else {
#pragma unroll
            for (int r = 0; r < 8; r++) fa[r] = Ab[k0 * op.a_ks + goff[r]];
        }
        fb0 = *(const float4*)(pB + k0 * op.ldb);
        fb1 = *(const float4*)(pB + (k0 + 8) * op.ldb);
    };
    auto stos = [&](int bs) {
        if (mode == 0) {
#pragma unroll
            for (int t = 0; t < 8; t++) As[bs][ak+t][am] = fa[t];
        } else if (mode == 1) {
            *(float4*)&As[bs][ak2][am4]   = make_float4(fa[0],fa[1],fa[2],fa[3]);
            *(float4*)&As[bs][ak2+8][am4] = make_float4(fa[4],fa[5],fa[6],fa[7]);
        } else {
#pragma unroll
            for (int r = 0; r < 8; r++) As[bs][gkk[r]][gmm[r]] = fa[r];
        }
        *(float4*)&Bs[bs][bk][bj4]   = fb0;
        *(float4*)&Bs[bs][bk+8][bj4] = fb1;
    };

    u64 acc2[8][4] = {};
    fetch(0); stos(0);
    __syncthreads();

    int nk = op.K >> 4, buf = 0;
    for (int t = 0; t < nk; t++) {
        bool more = (t + 1 < nk);
        if (more) fetch(t + 1);
#pragma unroll
        for (int kk = 0; kk < 16; kk++) {
            float av[8];
            *(float4*)(av)   = *(const float4*)&As[buf][kk][tm];
            *(float4*)(av+4) = *(const float4*)&As[buf][kk][tm+4];
            ulonglong2 b01 = *(const ulonglong2*)&Bs[buf][kk][tn];
            ulonglong2 b23 = *(const ulonglong2*)&Bs[buf][kk][tn+4];
            u64 bv[4] = {b01.x, b01.y, b23.x, b23.y};
#pragma unroll
            for (int i = 0; i < 8; i++) {
                u64 ad = dup2(av[i]);
#pragma unroll
                for (int j = 0; j < 4; j++)
                    acc2[i][j] = ffma2(ad, bv[j], acc2[i][j]);
            }
        }
        if (more) { stos(buf ^ 1); __syncthreads(); buf ^= 1; }
    }

    float acc[8][8];
#pragma unroll
    for (int i = 0; i < 8; i++)
#pragma unroll
        for (int j = 0; j < 4; j++)
            unpack2(acc2[i][j], acc[i][2*j], acc[i][2*j+1]);

    float bj[8], bm[8];
#pragma unroll
    for (int j = 0; j < 8; j++) bj[j] = op.bias_j ? op.bias_j[j0+tn+j] : 0.f;
#pragma unroll
    for (int i = 0; i < 8; i++) bm[i] = op.bias_m ? op.bias_m[m0+tm+i] : 0.f;
    long cb = (long)bz * op.c_bs;
    if (op.c_js == 1) {
#pragma unroll
        for (int i = 0; i < 8; i++) {
            long off = cb + (long)(m0+tm+i)*op.c_ms + (j0+tn);
            float4 v0 = make_float4(acc[i][0]+bj[0]+bm[i], acc[i][1]+bj[1]+bm[i],
                                    acc[i][2]+bj[2]+bm[i], acc[i][3]+bj[3]+bm[i]);
            float4 v1 = make_float4(acc[i][4]+bj[4]+bm[i], acc[i][5]+bj[5]+bm[i],
                                    acc[i][6]+bj[6]+bm[i], acc[i][7]+bj[7]+bm[i]);
            if (op.addend) {
                float4 a0 = *(const float4*)&op.addend[off];
                float4 a1 = *(const float4*)&op.addend[off+4];
                v0.x+=a0.x; v0.y+=a0.y; v0.z+=a0.z; v0.w+=a0.w;
                v1.x+=a1.x; v1.y+=a1.y; v1.z+=a1.z; v1.w+=a1.w;
            }
            *(float4*)&op.C[off]   = v0;
            *(float4*)&op.C[off+4] = v1;
        }
    } else {
#pragma unroll
        for (int i = 0; i < 8; i++)
#pragma unroll
            for (int j = 0; j < 8; j++) {
                long off = cb + (long)(m0+tm+i)*op.c_ms + (long)(j0+tn+j)*op.c_js;
                float v = acc[i][j] + bj[j] + bm[i];
                if (op.addend) v += op.addend[off];
                op.C[off] = v;
            }
    }
}

// ---------------- plain SGEMM kernel (final fused proj+pw) -------------------
__global__ void __launch_bounds__(256) k_sgemm(GemmOp op) {
    __shared__ float As[2][16][132];
    __shared__ float Bs[2][16][132];
    int bid = blockIdx.x;
    int per = op.tx * op.ty;
    int bz  = bid / per;
    int rem = bid - bz * per;
    int m0 = (rem / op.tx) * 128, j0 = (rem % op.tx) * 128;
    int tid = threadIdx.x;
    const float* Ab = op.A  + (long)bz * op.a_bs;
    const float* Bb = op.Bw + (long)bz * op.w_bs;
    int mode = (op.a_ks == 1) ? 0 : 1;

    int warp = tid >> 5, lane = tid & 31;
    int tm = (warp & 3) * 32 + (lane & 3) * 8;
    int tn = (warp >> 2) * 64 + (lane >> 2) * 8;
    int am  = tid >> 1, ak = (tid & 1) * 8;
    int am4 = (tid & 31) * 4, ak2 = tid >> 5;
    int bj4 = (tid & 31) * 4, bk  = tid >> 5;

    const float* pA = (mode == 0) ? (Ab + (long)(m0 + am) * op.a_ms + ak)
                                  : (Ab + (long)ak2 * op.a_ks + m0 + am4);
    const float* pB = Bb + (long)bk * op.ldb + j0 + bj4;

    float fa[8]; float4 fb0, fb1;
    auto fetch = [&](int t) {
        long k0 = (long)t * 16;
        if (mode == 0) {
            float4 v0 = *(const float4*)(pA + k0);
            float4 v1 = *(const float4*)(pA + k0 + 4);
            fa[0]=v0.x; fa[1]=v0.y; fa[2]=v0.z; fa[3]=v0.w;
            fa[4]=v1.x; fa[5]=v1.y; fa[6]=v1.z; fa[7]=v1.w;
        } else {
            float4 v0 = *(const float4*)(pA + k0 * op.a_ks);
            float4 v1 = *(const float4*)(pA + (k0 + 8) * op.a_ks);
            fa[0]=v0.x; fa[1]=v0.y; fa[2]=v0.z; fa[3]=v0.w;
            fa[4]=v1.x; fa[5]=v1.y; fa[6]=v1.z; fa[7]=v1.w;
        }
        fb0 = *(const float4*)(pB + k0 * op.ldb);
        fb1 = *(const float4*)(pB + (k0 + 8) * op.ldb);
    };
    auto stos = [&](int bs) {
        if (mode == 0) {
#pragma unroll
            for (int t = 0; t < 8; t++) As[bs][ak+t][am] = fa[t];
        } else {
            *(float4*)&As[bs][ak2][am4]   = make_float4(fa[0],fa[1],fa[2],fa[3]);
            *(float4*)&As[bs][ak2+8][am4] = make_float4(fa[4],fa[5],fa[6],fa[7]);
        }
        *(float4*)&Bs[bs][bk][bj4]   = fb0;
        *(float4*)&Bs[bs][bk+8][bj4] = fb1;
    };

    u64 acc2[8][4] = {};
    fetch(0); stos(0);
    __syncthreads();
    int nk = op.K >> 4, buf = 0;
    for (int t = 0; t < nk; t++) {
        bool more = (t + 1 < nk);
        if (more) fetch(t + 1);
#pragma unroll
        for (int kk = 0; kk < 16; kk++) {
            float av[8];
            *(float4*)(av)   = *(const float4*)&As[buf][kk][tm];
            *(float4*)(av+4) = *(const float4*)&As[buf][kk][tm+4];
            ulonglong2 b01 = *(const ulonglong2*)&Bs[buf][kk][tn];
            ulonglong2 b23 = *(const ulonglong2*)&Bs[buf][kk][tn+4];
            u64 bv[4] = {b01.x, b01.y, b23.x, b23.y};
#pragma unroll
            for (int i = 0; i < 8; i++) {
                u64 ad = dup2(av[i]);
#pragma unroll
                for (int j = 0; j < 4; j++)
                    acc2[i][j] = ffma2(ad, bv[j], acc2[i][j]);
            }
        }
        if (more) { stos(buf ^ 1); __syncthreads(); buf ^= 1; }
    }
    float acc[8][8];
#pragma unroll
    for (int i = 0; i < 8; i++)
#pragma unroll
        for (int j = 0; j < 4; j++)
            unpack2(acc2[i][j], acc[i][2*j], acc[i][2*j+1]);
    float bj[8], bm[8];
#pragma unroll
    for (int j = 0; j < 8; j++) bj[j] = op.bias_j ? op.bias_j[j0+tn+j] : 0.f;
#pragma unroll
    for (int i = 0; i < 8; i++) bm[i] = op.bias_m ? op.bias_m[m0+tm+i] : 0.f;
    long cb = (long)bz * op.c_bs;
#pragma unroll
    for (int i = 0; i < 8; i++) {
        long off = cb + (long)(m0+tm+i)*op.c_ms + (j0+tn);
        float4 v0 = make_float4(acc[i][0]+bj[0]+bm[i], acc[i][1]+bj[1]+bm[i],
                                acc[i][2]+bj[2]+bm[i], acc[i][3]+bj[3]+bm[i]);
        float4 v1 = make_float4(acc[i][4]+bj[4]+bm[i], acc[i][5]+bj[5]+bm[i],
                                acc[i][6]+bj[6]+bm[i], acc[i][7]+bj[7]+bm[i]);
        if (op.addend) {
            float4 a0 = *(const float4*)&op.addend[off];
            float4 a1 = *(const float4*)&op.addend[off+4];
            v0.x+=a0.x; v0.y+=a0.y; v0.z+=a0.z; v0.w+=a0.w;
            v1.x+=a1.x; v1.y+=a1.y; v1.z+=a1.z; v1.w+=a1.w;
        }
        *(float4*)&op.C[off]   = v0;
        *(float4*)&op.C[off+4] = v1;
    }
}

// ---------------- merged dwconv (blocks 0..1023) + attention (1024..1151) ----
#define NDW 1024
__global__ void __launch_bounds__(512) k_attn_dw(const float* __restrict__ w_dw,
                                                 const float* __restrict__ b_dw) {
    __shared__ float Ks[KTOP*HD];   // 16 KB
    __shared__ float Vs[KTOP*HD];   // 16 KB
    int tid = threadIdx.x;

    if (blockIdx.x < NDW) {
        // ---- dwconv role: 4 outputs/thread, float4 rows -> g_cat rows 256..511
        int i = blockIdx.x * 512 + tid;     // 0 .. 524287
        int xq = i & 3, y = (i >> 2) & 15, z = (i >> 6) & 15;
        int c = (i >> 10) & 255, b = i >> 18;
        const float* base = g_vvol + ((long)b*CC + c)*NN;
        float w27[27];
#pragma unroll
        for (int t = 0; t < 27; t++) w27[t] = w_dw[c*27 + t];
        float bias = b_dw[c];
        float o0 = bias, o1 = bias, o2 = bias, o3 = bias;
        int x0 = xq * 4;
#pragma unroll
        for (int dz = 0; dz < 3; dz++) {
            int zz = z + dz - 1; if (zz < 0 || zz > 15) continue;
#pragma unroll
            for (int dy = 0; dy < 3; dy++) {
                int yy = y + dy - 1; if (yy < 0 || yy > 15) continue;
                const float* r = base + zz*256 + yy*16 + x0;
                float4 m4 = *(const float4*)r;
                float xl = (xq > 0) ? r[-1] : 0.f;
                float xr = (xq < 3) ? r[4]  : 0.f;
                float wl = w27[dz*9+dy*3], wm = w27[dz*9+dy*3+1], wr = w27[dz*9+dy*3+2];
                o0 += wl*xl   + wm*m4.x + wr*m4.y;
                o1 += wl*m4.x + wm*m4.y + wr*m4.z;
                o2 += wl*m4.y + wm*m4.z + wr*m4.w;
                o3 += wl*m4.z + wm*m4.w + wr*xr;
            }
        }
        *(float4*)&g_cat[((long)b*512 + 256 + c)*NN + z*256 + y*16 + x0]
            = make_float4(o0,o1,o2,o3);
        return;
    }

    // ---- attention role ----
    int abid = blockIdx.x - NDW;            // 0..127
    int nt = abid & 1, h = (abid >> 1) & 31, b = abid >> 6;
    const float* kgb = g_kvg + (long)b*KTOP*512 + h*HD;
    const float* vgb = kgb + CC;
    {
        int k = tid;
        *(float4*)(Ks + k*8)     = *(const float4*)(kgb + (long)k*512);
        *(float4*)(Ks + k*8 + 4) = *(const float4*)(kgb + (long)k*512 + 4);
        *(float4*)(Vs + k*8)     = *(const float4*)(vgb + (long)k*512);
        *(float4*)(Vs + k*8 + 4) = *(const float4*)(vgb + (long)k*512 + 4);
    }
    __syncthreads();
    const float cs = 0.35355339059327373f * 1.4426950408889634f; // scale*log2e
    u64 qr2[4][4], acc2[4][4] = {};
    float l[4] = {0,0,0,0};
    int n0 = nt * 2048;
#pragma unroll
    for (int i = 0; i < 4; i++) {
        int n = n0 + tid + 512*i;
        const float* qp = g_q + ((long)b*NN + n)*CC + h*HD;
        float4 qa = *(const float4*)qp;
        float4 qb = *(const float4*)(qp + 4);
        qr2[i][0] = pack2(qa.x*cs, qa.y*cs);
        qr2[i][1] = pack2(qa.z*cs, qa.w*cs);
        qr2[i][2] = pack2(qb.x*cs, qb.y*cs);
        qr2[i][3] = pack2(qb.z*cs, qb.w*cs);
    }
#pragma unroll 2
    for (int k = 0; k < KTOP; k++) {
        ulonglong2 k01 = *(const ulonglong2*)(Ks + k*8);
        ulonglong2 k23 = *(const ulonglong2*)(Ks + k*8 + 4);
        ulonglong2 v01 = *(const ulonglong2*)(Vs + k*8);
        ulonglong2 v23 = *(const ulonglong2*)(Vs + k*8 + 4);
#pragma unroll
        for (int i = 0; i < 4; i++) {
            u64 t2 = mul2(qr2[i][0], k01.x);
            t2 = ffma2(qr2[i][1], k01.y, t2);
            t2 = ffma2(qr2[i][2], k23.x, t2);
            t2 = ffma2(qr2[i][3], k23.y, t2);
            float slo, shi; unpack2(t2, slo, shi);
            float p = ex2f(slo + shi);
            l[i] += p;
            u64 pp = dup2(p);
            acc2[i][0] = ffma2(pp, v01.x, acc2[i][0]);
            acc2[i][1] = ffma2(pp, v01.y, acc2[i][1]);
            acc2[i][2] = ffma2(pp, v23.x, acc2[i][2]);
            acc2[i][3] = ffma2(pp, v23.y, acc2[i][3]);
        }
    }
#pragma unroll
    for (int i = 0; i < 4; i++) {
        int n = n0 + tid + 512*i;
        float inv = 1.0f / l[i];
        float a[8];
#pragma unroll
        for (int d = 0; d < 4; d++) unpack2(acc2[i][d], a[2*d], a[2*d+1]);
        float* op = g_cat + (long)b*2*CN + (long)(h*HD)*NN + n;
#pragma unroll
        for (int d = 0; d < 8; d++) op[(long)d*NN] = a[d]*inv;
    }
}

// ---------------- launcher ----------------
extern "C" void kernel_launch(void* const* d_in, const int* in_sizes, int n_in,
                              void* d_out, int out_size) {
    const float* x_kv  = (const float*)d_in[0];
    const float* x_q   = (const float*)d_in[1];
    const float* w_spa = (const float*)d_in[2];
    const float* w_kv  = (const float*)d_in[3];
    const float* b_kv  = (const float*)d_in[4];
    const float* w_q   = (const float*)d_in[5];
    const float* b_q   = (const float*)d_in[6];
    const float* w_proj= (const float*)d_in[7];
    const float* b_proj= (const float*)d_in[8];
    const float* w_dw  = (const float*)d_in[9];
    const float* b_dw  = (const float*)d_in[10];
    const float* w_pw  = (const float*)d_in[11];
    const float* b_pw  = (const float*)d_in[12];
    float* out = (float*)d_out;

    float *q, *kvg, *vvol, *cat, *wcat, *bcat;
    int *idx;
    cudaGetSymbolAddress((void**)&q,    g_q);
    cudaGetSymbolAddress((void**)&kvg,  g_kvg);
    cudaGetSymbolAddress((void**)&vvol, g_vvol);
    cudaGetSymbolAddress((void**)&cat,  g_cat);
    cudaGetSymbolAddress((void**)&wcat, g_wcat);
    cudaGetSymbolAddress((void**)&bcat, g_bcat);
    cudaGetSymbolAddress((void**)&idx,  g_idx);

    // scoring path
    k_reduce<<<dim3(64, 2), 256>>>(x_kv);
    k_spa<<<32, 256>>>(w_spa);

    // mega: topk (blocks 0-1) + Q/V/KV gemms (2-289) + wcat prep (290-417)
    GemmOp opQ  = { x_q, 1L, (long)NN, (long)CN, nullptr, 0L,
                    w_q, 256, 0L, b_q, nullptr, nullptr,
                    q, (long)CC, 1L, (long)CN, CC, 2, 32 };
    GemmOp opV  = { x_kv, 1L, (long)NN, (long)CN, nullptr, 0L,
                    w_kv + CC, 512, 0L, b_kv + CC, nullptr, nullptr,
                    vvol, 1L, (long)NN, (long)CN, CC, 2, 32 };
    GemmOp opKV = { x_kv, 1L, (long)NN, (long)CN, idx, (long)KTOP,
                    w_kv, 512, 0L, b_kv, nullptr, nullptr,
                    kvg, 512L, 1L, (long)(KTOP*512), CC, 4, 4 };
    k_mega<<<2 + 288 + 128, 256>>>(opQ, opV, opKV, w_proj, w_pw, b_proj, b_pw);

    // merged dwconv (first) + attention (backfill); writes both halves of g_cat
    k_attn_dw<<<NDW + 128, 512>>>(w_dw, b_dw);

    // fused proj+pw GEMM (K=512): out[b][c][n] = wcat^T @ g_cat + bcat
    GemmOp opF  = { wcat, 1L, 256L, 0L, nullptr, 0L,
                    cat, 4096, (long)(2*CN), nullptr, bcat, nullptr,
                    out, 4096L, 1L, (long)CN, 512, 32, 2 };
    k_sgemm<<<128, 256>>>(opF);
}

// round 15
// speedup vs baseline: 1.0239x; 1.0239x over previous
#include <cuda_runtime.h>
#include <math.h>

#define BATCH 2
#define CC 256
#define NN 4096
#define HEADS 32
#define HD 8
#define KTOP 512
#define CN (CC*NN)

typedef unsigned long long u64;

// ---- packed f32x2 helpers ----
__device__ __forceinline__ u64 pack2(float lo, float hi) {
    u64 r; asm("mov.b64 %0, {%1, %2};" : "=l"(r) : "f"(lo), "f"(hi)); return r;
}
__device__ __forceinline__ u64 dup2(float a) {
    u64 r; asm("mov.b64 %0, {%1, %1};" : "=l"(r) : "f"(a)); return r;
}
__device__ __forceinline__ void unpack2(u64 p, float& lo, float& hi) {
    asm("mov.b64 {%0, %1}, %2;" : "=f"(lo), "=f"(hi) : "l"(p));
}
__device__ __forceinline__ u64 ffma2(u64 a, u64 b, u64 c) {
    u64 d; asm("fma.rn.f32x2 %0, %1, %2, %3;" : "=l"(d) : "l"(a), "l"(b), "l"(c)); return d;
}
__device__ __forceinline__ u64 mul2(u64 a, u64 b) {
    u64 d; asm("mul.rn.f32x2 %0, %1, %2;" : "=l"(d) : "l"(a), "l"(b)); return d;
}
__device__ __forceinline__ float ex2f(float x) {
    float r; asm("ex2.approx.f32 %0, %1;" : "=f"(r) : "f"(x)); return r;
}

// ---------------- scratch (device globals; no allocation) ----------------
__device__ float g_avgmax[BATCH*2*NN];
__device__ float g_scores[BATCH*NN];
__device__ int   g_idx[BATCH*KTOP];
__device__ int   g_tflag[BATCH];           // 0 -> topk pending; 1 -> idx ready
__device__ float g_q[BATCH*NN*CC];
__device__ float g_kvg[BATCH*KTOP*2*CC];   // [b][k][0:256]=K, [256:512]=V
__device__ float g_vvol[BATCH*CN];
__device__ float g_cat[BATCH*2*CN];        // [b][0:256]=attn_t, [256:512]=dw  (C,N)
__device__ float g_wcat[2*CC*CC];          // [k][c]: k<256 w_proj, k>=256 w_pw^T
__device__ float g_bcat[CC];               // b_proj + b_pw

// ---------------- 1. channel avg/max reduce (4-way c-split) ----------------
__global__ void k_reduce(const float* __restrict__ x) {
    __shared__ float ssum[4][64], smax[4][64];
    int b = blockIdx.y;
    int n0 = blockIdx.x * 64;
    int cq = threadIdx.x >> 6;
    int nn = threadIdx.x & 63;
    const float* p = x + (long)b*CN + n0 + nn;
    float s = 0.f, mx = -INFINITY;
#pragma unroll 8
    for (int c = cq*64; c < cq*64 + 64; c++) {
        float v = p[(long)c*NN]; s += v; mx = fmaxf(mx, v);
    }
    ssum[cq][nn] = s; smax[cq][nn] = mx;
    __syncthreads();
    if (cq == 0) {
        s = ssum[0][nn] + ssum[1][nn] + ssum[2][nn] + ssum[3][nn];
        mx = fmaxf(fmaxf(smax[0][nn], smax[1][nn]), fmaxf(smax[2][nn], smax[3][nn]));
        g_avgmax[(b*2+0)*NN + n0 + nn] = s * (1.0f/CC);
        g_avgmax[(b*2+1)*NN + n0 + nn] = mx;
    }
}

// ---------------- 2. 7x7x7 spatial conv (2ch -> 1ch) + sigmoid ----------------
__global__ void k_spa(const float* __restrict__ w_spa) {
    __shared__ float w[686];
    int tid = threadIdx.x;
    for (int l = tid; l < 686; l += blockDim.x) w[l] = w_spa[l];
    __syncthreads();
    int i = blockIdx.x * blockDim.x + tid;
    if (i >= BATCH*NN) return;
    int b = i >> 12, n = i & (NN-1);
    int z = n >> 8, y = (n >> 4) & 15, x0 = n & 15;
    float s = 0.f;
    for (int ci = 0; ci < 2; ci++) {
        const float* in = g_avgmax + (b*2+ci)*NN;
        const float* wc = w + ci*343;
        for (int dz = 0; dz < 7; dz++) {
            int zz = z + dz - 3; if (zz < 0 || zz > 15) continue;
            for (int dy = 0; dy < 7; dy++) {
                int yy = y + dy - 3; if (yy < 0 || yy > 15) continue;
                const float* row = in + zz*256 + yy*16;
                const float* wr = wc + dz*49 + dy*7;
                for (int dx = 0; dx < 7; dx++) {
                    int xx = x0 + dx - 3; if (xx < 0 || xx > 15) continue;
                    s += wr[dx] * row[xx];
                }
            }
        }
    }
    g_scores[i] = 1.0f / (1.0f + __expf(-s));
}

// ---------------- GemmOp ----------------
struct GemmOp {
    const float* A; long a_ms, a_ks, a_bs;
    const int* rowidx; long ridx_bs;
    const float* Bw; int ldb; long w_bs;
    const float* bias_j; const float* bias_m; const float* addend;
    float* C; long c_ms, c_js, c_bs;
    int K; int tx; int ty;
};

// ---------------- topk role (256 threads): radix select, sets g_tflag --------
__device__ void topk_role(int b, char* sraw) {
    unsigned* skey = (unsigned*)sraw;                   // 16384 B
    unsigned* hist = (unsigned*)(sraw + 16384);         // 1024 B
    unsigned* scan = (unsigned*)(sraw + 17408);         // 1024 B
    unsigned* S    = (unsigned*)(sraw + 18432);         // sel,need,neednxt,cnt,tie
    int tid = threadIdx.x;
    const unsigned* keys = (const unsigned*)g_scores + b*NN;
    for (int i = tid; i < NN; i += 256) skey[i] = keys[i];
    if (tid == 0) S[1] = KTOP;
    __syncthreads();
    unsigned prefix = 0, pmask = 0;
    for (int shift = 24; shift >= 0; shift -= 8) {
        hist[tid] = 0;
        __syncthreads();
        for (int i = tid; i < NN; i += 256) {
            unsigned k = skey[i];
            if ((k & pmask) == prefix) atomicAdd(&hist[(k >> shift) & 255u], 1u);
        }
        __syncthreads();
        scan[tid] = hist[255 - tid];
        __syncthreads();
#pragma unroll
        for (int off = 1; off < 256; off <<= 1) {
            unsigned add = (tid >= off) ? scan[tid - off] : 0u;
            __syncthreads();
            scan[tid] += add;
            __syncthreads();
        }
        unsigned need = S[1];
        unsigned suf = scan[tid], above = tid ? scan[tid - 1] : 0u;
        if (suf >= need && above < need) { S[0] = 255u - tid; S[2] = need - above; }
        __syncthreads();
        prefix |= S[0] << shift;
        pmask  |= 255u << shift;
        if (tid == 0) S[1] = S[2];
        __syncthreads();
    }
    if (tid == 0) { S[3] = 0; S[4] = 0; }
    __syncthreads();
    unsigned tietake = S[1];
    for (int i = tid; i < NN; i += 256) {
        unsigned k = skey[i];
        if (k > prefix) {
            unsigned p = atomicAdd(&S[3], 1u);
            g_idx[b*KTOP + p] = i;
        } else if (k == prefix) {
            unsigned t = atomicAdd(&S[4], 1u);
            if (t < tietake) {
                unsigned p = atomicAdd(&S[3], 1u);
                g_idx[b*KTOP + p] = i;
            }
        }
    }
    __threadfence();
    __syncthreads();
    if (tid == 0) atomicExch(&g_tflag[b], 1);
}

// ---------------- mega kernel: topk(2) + QVK gemms(288) + wcat prep(128) -----
__global__ void __launch_bounds__(256) k_mega(
    GemmOp o1, GemmOp o2, GemmOp o3,
    const float* __restrict__ w_proj, const float* __restrict__ w_pw,
    const float* __restrict__ b_proj, const float* __restrict__ b_pw)
{
    __shared__ __align__(16) char sraw[34816];
    int bid = blockIdx.x;
    int tid = threadIdx.x;

    if (bid < 2) { topk_role(bid, sraw); return; }
    bid -= 2;
    if (bid >= 288) {                       // prep role: 128 blocks x 1024 elems
        int e0 = (bid - 288) * 1024 + tid * 4;
#pragma unroll
        for (int j = 0; j < 4; j++) {
            int e = e0 + j;
            int k = e >> 8, c = e & 255;
            g_wcat[e] = (k < CC) ? w_proj[k*CC + c] : w_pw[c*CC + (k - CC)];
            if (e < CC) g_bcat[e] = b_proj[e] + b_pw[e];
        }
        return;
    }

    // ---- GEMM role ----
    float (&As)[2][16][132] = *reinterpret_cast<float(*)[2][16][132]>(sraw);
    float (&Bs)[2][16][132] = *reinterpret_cast<float(*)[2][16][132]>(sraw + 16896);
    int*  sidx = (int*)(sraw + 33792);

    GemmOp op; int local;
    if (bid < 128)      { op = o1; local = bid; }
    else if (bid < 256) { op = o2; local = bid - 128; }
    else                { op = o3; local = bid - 256; }
    int per = op.tx * op.ty;
    int bz  = local / per;
    int rem = local - bz * per;
    int m0 = (rem / op.tx) * 128, j0 = (rem % op.tx) * 128;

    const float* Ab = op.A  + (long)bz * op.a_bs;
    const float* Bb = op.Bw + (long)bz * op.w_bs;

    int mode = op.rowidx ? 2 : ((op.a_ks == 1) ? 0 : 1);

    int warp = tid >> 5, lane = tid & 31;
    int tm = (warp & 3) * 32 + (lane & 3) * 8;
    int tn = (warp >> 2) * 64 + (lane >> 2) * 8;

    int am  = tid >> 1, ak = (tid & 1) * 8;     // mode 0
    int am4 = (tid & 31) * 4, ak2 = tid >> 5;   // mode 1
    int bj4 = (tid & 31) * 4, bk  = tid >> 5;   // B

    long goff[8]; int gmm[8], gkk[8];
    if (mode == 2) {
        // wait for topk blocks (lowest bids, resident first) to publish g_idx
        if (tid == 0) { while (atomicAdd(&g_tflag[bz], 0) == 0) {} }
        __syncthreads();
        if (tid < 128) sidx[tid] = op.rowidx[(long)bz * op.ridx_bs + m0 + tid];
        __syncthreads();
#pragma unroll
        for (int r = 0; r < 8; r++) {
            int l = tid + r * 256;
            gmm[r] = l & 127; gkk[r] = l >> 7;
            goff[r] = (long)gkk[r] * op.a_ks + sidx[gmm[r]];
        }
    }

    const float* pA = Ab;
    if (mode == 0)      pA = Ab + (long)(m0 + am) * op.a_ms + ak;
    else if (mode == 1) pA = Ab + (long)ak2 * op.a_ks + m0 + am4;
    const float* pB = Bb + (long)bk * op.ldb + j0 + bj4;

    float fa[8]; float4 fb0, fb1;
    auto fetch = [&](int t) {
        long k0 = (long)t * 16;
        if (mode == 0) {
            float4 v0 = *(const float4*)(pA + k0);
            float4 v1 = *(const float4*)(pA + k0 + 4);
            fa[0]=v0.x; fa[1]=v0.y; fa[2]=v0.z; fa[3]=v0.w;
            fa[4]=v1.x; fa[5]=v1.y; fa[6]=v1.z; fa[7]=v1.w;
        } else if (mode == 1) {
            float4 v0 = *(const float4*)(pA + k0 * op.a_ks);
            float4 v1 = *(const float4*)(pA + (k0 + 8) * op.a_ks);
            fa[0]=v0.x; fa[1]=v0.y; fa[2]=v0.z; fa[3]=v0.w;
            fa[4]=v1.x; fa[5]=v1.y; fa[6]=v1.z; fa[7]=v1.w;
        } else {
#pragma unroll
            for (int r = 0; r < 8; r++) fa[r] = Ab[k0 * op.a_ks + goff[r]];
        }
        fb0 = *(const float4*)(pB + k0 * op.ldb);
        fb1 = *(const float4*)(pB + (k0 + 8) * op.ldb);
    };
    auto stos = [&](int bs) {
        if (mode == 0) {
#pragma unroll
            for (int t = 0; t < 8; t++) As[bs][ak+t][am] = fa[t];
        } else if (mode == 1) {
            *(float4*)&As[bs][ak2][am4]   = make_float4(fa[0],fa[1],fa[2],fa[3]);
            *(float4*)&As[bs][ak2+8][am4] = make_float4(fa[4],fa[5],fa[6],fa[7]);
        } else {
#pragma unroll
            for (int r = 0; r < 8; r++) As[bs][gkk[r]][gmm[r]] = fa[r];
        }
        *(float4*)&Bs[bs][bk][bj4]   = fb0;
        *(float4*)&Bs[bs][bk+8][bj4] = fb1;
    };

    u64 acc2[8][4] = {};
    fetch(0); stos(0);
    __syncthreads();

    int nk = op.K >> 4, buf = 0;
    for (int t = 0; t < nk; t++) {
        bool more = (t + 1 < nk);
        if (more) fetch(t + 1);
#pragma unroll
        for (int kk = 0; kk < 16; kk++) {
            float av[8];
            *(float4*)(av)   = *(const float4*)&As[buf][kk][tm];
            *(float4*)(av+4) = *(const float4*)&As[buf][kk][tm+4];
            ulonglong2 b01 = *(const ulonglong2*)&Bs[buf][kk][tn];
            ulonglong2 b23 = *(const ulonglong2*)&Bs[buf][kk][tn+4];
            u64 bv[4] = {b01.x, b01.y, b23.x, b23.y};
#pragma unroll
            for (int i = 0; i < 8; i++) {
                u64 ad = dup2(av[i]);
#pragma unroll
                for (int j = 0; j < 4; j++)
                    acc2[i][j] = ffma2(ad, bv[j], acc2[i][j]);
            }
        }
        if (more) { stos(buf ^ 1); __syncthreads(); buf ^= 1; }
    }

    float acc[8][8];
#pragma unroll
    for (int i = 0; i < 8; i++)
#pragma unroll
        for (int j = 0; j < 4; j++)
            unpack2(acc2[i][j], acc[i][2*j], acc[i][2*j+1]);

    float bj[8], bm[8];
#pragma unroll
    for (int j = 0; j < 8; j++) bj[j] = op.bias_j ? op.bias_j[j0+tn+j] : 0.f;
#pragma unroll
    for (int i = 0; i < 8; i++) bm[i] = op.bias_m ? op.bias_m[m0+tm+i] : 0.f;
    long cb = (long)bz * op.c_bs;
    if (op.c_js == 1) {
#pragma unroll
        for (int i = 0; i < 8; i++) {
            long off = cb + (long)(m0+tm+i)*op.c_ms + (j0+tn);
            float4 v0 = make_float4(acc[i][0]+bj[0]+bm[i], acc[i][1]+bj[1]+bm[i],
                                    acc[i][2]+bj[2]+bm[i], acc[i][3]+bj[3]+bm[i]);
            float4 v1 = make_float4(acc[i][4]+bj[4]+bm[i], acc[i][5]+bj[5]+bm[i],
                                    acc[i][6]+bj[6]+bm[i], acc[i][7]+bj[7]+bm[i]);
            if (op.addend) {
                float4 a0 = *(const float4*)&op.addend[off];
                float4 a1 = *(const float4*)&op.addend[off+4];
                v0.x+=a0.x; v0.y+=a0.y; v0.z+=a0.z; v0.w+=a0.w;
                v1.x+=a1.x; v1.y+=a1.y; v1.z+=a1.z; v1.w+=a1.w;
            }
            *(float4*)&op.C[off]   = v0;
            *(float4*)&op.C[off+4] = v1;
        }
    } else {
#pragma unroll
        for (int i = 0; i < 8; i++)
#pragma unroll
            for (int j = 0; j < 8; j++) {
                long off = cb + (long)(m0+tm+i)*op.c_ms + (long)(j0+tn+j)*op.c_js;
                float v = acc[i][j] + bj[j] + bm[i];
                if (op.addend) v += op.addend[off];
                op.C[off] = v;
            }
    }
}

// ---------------- plain SGEMM kernel (final fused proj+pw) -------------------
__global__ void __launch_bounds__(256) k_sgemm(GemmOp op) {
    __shared__ float As[2][16][132];
    __shared__ float Bs[2][16][132];
    int bid = blockIdx.x;
    int per = op.tx * op.ty;
    int bz  = bid / per;
    int rem = bid - bz * per;
    int m0 = (rem / op.tx) * 128, j0 = (rem % op.tx) * 128;
    int tid = threadIdx.x;
    const float* Ab = op.A  + (long)bz * op.a_bs;
    const float* Bb = op.Bw + (long)bz * op.w_bs;
    int mode = (op.a_ks == 1) ? 0 : 1;

    int warp = tid >> 5, lane = tid & 31;
    int tm = (warp & 3) * 32 + (lane & 3) * 8;
    int tn = (warp >> 2) * 64 + (lane >> 2) * 8;
    int am  = tid >> 1, ak = (tid & 1) * 8;
    int am4 = (tid & 31) * 4, ak2 = tid >> 5;
    int bj4 = (tid & 31) * 4, bk  = tid >> 5;

    const float* pA = (mode == 0) ? (Ab + (long)(m0 + am) * op.a_ms + ak)
                                  : (Ab + (long)ak2 * op.a_ks + m0 + am4);
    const float* pB = Bb + (long)bk * op.ldb + j0 + bj4;

    float fa[8]; float4 fb0, fb1;
    auto fetch = [&](int t) {
        long k0 = (long)t * 16;
        if (mode == 0) {
            float4 v0 = *(const float4*)(pA + k0);
            float4 v1 = *(const float4*)(pA + k0 + 4);
            fa[0]=v0.x; fa[1]=v0.y; fa[2]=v0.z; fa[3]=v0.w;
            fa[4]=v1.x; fa[5]=v1.y; fa[6]=v1.z; fa[7]=v1.w;
        } else {
            float4 v0 = *(const float4*)(pA + k0 * op.a_ks);
            float4 v1 = *(const float4*)(pA + (k0 + 8) * op.a_ks);
            fa[0]=v0.x; fa[1]=v0.y; fa[2]=v0.z; fa[3]=v0.w;
            fa[4]=v1.x; fa[5]=v1.y; fa[6]=v1.z; fa[7]=v1.w;
        }
        fb0 = *(const float4*)(pB + k0 * op.ldb);
        fb1 = *(const float4*)(pB + (k0 + 8) * op.ldb);
    };
    auto stos = [&](int bs) {
        if (mode == 0) {
#pragma unroll
            for (int t = 0; t < 8; t++) As[bs][ak+t][am] = fa[t];
        } else {
            *(float4*)&As[bs][ak2][am4]   = make_float4(fa[0],fa[1],fa[2],fa[3]);
            *(float4*)&As[bs][ak2+8][am4] = make_float4(fa[4],fa[5],fa[6],fa[7]);
        }
        *(float4*)&Bs[bs][bk][bj4]   = fb0;
        *(float4*)&Bs[bs][bk+8][bj4] = fb1;
    };

    u64 acc2[8][4] = {};
    fetch(0); stos(0);
    __syncthreads();
    int nk = op.K >> 4, buf = 0;
    for (int t = 0; t < nk; t++) {
        bool more = (t + 1 < nk);
        if (more) fetch(t + 1);
#pragma unroll
        for (int kk = 0; kk < 16; kk++) {
            float av[8];
            *(float4*)(av)   = *(const float4*)&As[buf][kk][tm];
            *(float4*)(av+4) = *(const float4*)&As[buf][kk][tm+4];
            ulonglong2 b01 = *(const ulonglong2*)&Bs[buf][kk][tn];
            ulonglong2 b23 = *(const ulonglong2*)&Bs[buf][kk][tn+4];
            u64 bv[4] = {b01.x, b01.y, b23.x, b23.y};
#pragma unroll
            for (int i = 0; i < 8; i++) {
                u64 ad = dup2(av[i]);
#pragma unroll
                for (int j = 0; j < 4; j++)
                    acc2[i][j] = ffma2(ad, bv[j], acc2[i][j]);
            }
        }
        if (more) { stos(buf ^ 1); __syncthreads(); buf ^= 1; }
    }
    float acc[8][8];
#pragma unroll
    for (int i = 0; i < 8; i++)
#pragma unroll
        for (int j = 0; j < 4; j++)
            unpack2(acc2[i][j], acc[i][2*j], acc[i][2*j+1]);
    float bj[8], bm[8];
#pragma unroll
    for (int j = 0; j < 8; j++) bj[j] = op.bias_j ? op.bias_j[j0+tn+j] : 0.f;
#pragma unroll
    for (int i = 0; i < 8; i++) bm[i] = op.bias_m ? op.bias_m[m0+tm+i] : 0.f;
    long cb = (long)bz * op.c_bs;
#pragma unroll
    for (int i = 0; i < 8; i++) {
        long off = cb + (long)(m0+tm+i)*op.c_ms + (j0+tn);
        float4 v0 = make_float4(acc[i][0]+bj[0]+bm[i], acc[i][1]+bj[1]+bm[i],
                                acc[i][2]+bj[2]+bm[i], acc[i][3]+bj[3]+bm[i]);
        float4 v1 = make_float4(acc[i][4]+bj[4]+bm[i], acc[i][5]+bj[5]+bm[i],
                                acc[i][6]+bj[6]+bm[i], acc[i][7]+bj[7]+bm[i]);
        if (op.addend) {
            float4 a0 = *(const float4*)&op.addend[off];
            float4 a1 = *(const float4*)&op.addend[off+4];
            v0.x+=a0.x; v0.y+=a0.y; v0.z+=a0.z; v0.w+=a0.w;
            v1.x+=a1.x; v1.y+=a1.y; v1.z+=a1.z; v1.w+=a1.w;
        }
        *(float4*)&op.C[off]   = v0;
        *(float4*)&op.C[off+4] = v1;
    }
}

// ---------------- depthwise 3x3x3 conv (256 thr, high occupancy) -------------
__global__ void k_dwconv(const float* __restrict__ w_dw, const float* __restrict__ b_dw) {
    int i = blockIdx.x * blockDim.x + threadIdx.x;   // BATCH*CC*16*16*4
    int xq = i & 3, y = (i >> 2) & 15, z = (i >> 6) & 15, c = (i >> 10) & 255, b = i >> 18;
    const float* base = g_vvol + ((long)b*CC + c)*NN;
    float w27[27];
#pragma unroll
    for (int t = 0; t < 27; t++) w27[t] = w_dw[c*27 + t];
    float bias = b_dw[c];
    float o0 = bias, o1 = bias, o2 = bias, o3 = bias;
    int x0 = xq * 4;
#pragma unroll
    for (int dz = 0; dz < 3; dz++) {
        int zz = z + dz - 1; if (zz < 0 || zz > 15) continue;
#pragma unroll
        for (int dy = 0; dy < 3; dy++) {
            int yy = y + dy - 1; if (yy < 0 || yy > 15) continue;
            const float* r = base + zz*256 + yy*16 + x0;
            float4 m4 = *(const float4*)r;
            float xl = (xq > 0) ? r[-1] : 0.f;
            float xr = (xq < 3) ? r[4]  : 0.f;
            float wl = w27[dz*9+dy*3], wm = w27[dz*9+dy*3+1], wr = w27[dz*9+dy*3+2];
            o0 += wl*xl   + wm*m4.x + wr*m4.y;
            o1 += wl*m4.x + wm*m4.y + wr*m4.z;
            o2 += wl*m4.y + wm*m4.z + wr*m4.w;
            o3 += wl*m4.z + wm*m4.w + wr*xr;
        }
    }
    *(float4*)&g_cat[((long)b*512 + 256 + c)*NN + z*256 + y*16 + x0]
        = make_float4(o0,o1,o2,o3);
}

// ---------------- attention: FFMA2 + ex2; writes g_cat rows 0..255 -----------
__global__ void __launch_bounds__(512) k_attn() {
    __shared__ float Ks[KTOP*HD];   // 16 KB
    __shared__ float Vs[KTOP*HD];   // 16 KB
    int b = blockIdx.z, h = blockIdx.y, nt = blockIdx.x;
    int tid = threadIdx.x;
    const float* kgb = g_kvg + (long)b*KTOP*512 + h*HD;        // K at col h*8
    const float* vgb = kgb + CC;                               // V at col 256+h*8
    {
        int k = tid;   // 512 threads, 512 rows
        *(float4*)(Ks + k*8)     = *(const float4*)(kgb + (long)k*512);
        *(float4*)(Ks + k*8 + 4) = *(const float4*)(kgb + (long)k*512 + 4);
        *(float4*)(Vs + k*8)     = *(const float4*)(vgb + (long)k*512);
        *(float4*)(Vs + k*8 + 4) = *(const float4*)(vgb + (long)k*512 + 4);
    }
    __syncthreads();
    const float cs = 0.35355339059327373f * 1.4426950408889634f; // scale*log2e
    u64 qr2[4][4], acc2[4][4] = {};
    float l[4] = {0,0,0,0};
    int n0 = nt * 2048;
#pragma unroll
    for (int i = 0; i < 4; i++) {
        int n = n0 + tid + 512*i;
        const float* qp = g_q + ((long)b*NN + n)*CC + h*HD;
        float4 qa = *(const float4*)qp;
        float4 qb = *(const float4*)(qp + 4);
        qr2[i][0] = pack2(qa.x*cs, qa.y*cs);
        qr2[i][1] = pack2(qa.z*cs, qa.w*cs);
        qr2[i][2] = pack2(qb.x*cs, qb.y*cs);
        qr2[i][3] = pack2(qb.z*cs, qb.w*cs);
    }
#pragma unroll 2
    for (int k = 0; k < KTOP; k++) {
        ulonglong2 k01 = *(const ulonglong2*)(Ks + k*8);
        ulonglong2 k23 = *(const ulonglong2*)(Ks + k*8 + 4);
        ulonglong2 v01 = *(const ulonglong2*)(Vs + k*8);
        ulonglong2 v23 = *(const ulonglong2*)(Vs + k*8 + 4);
#pragma unroll
        for (int i = 0; i < 4; i++) {
            u64 t2 = mul2(qr2[i][0], k01.x);
            t2 = ffma2(qr2[i][1], k01.y, t2);
            t2 = ffma2(qr2[i][2], k23.x, t2);
            t2 = ffma2(qr2[i][3], k23.y, t2);
            float slo, shi; unpack2(t2, slo, shi);
            float p = ex2f(slo + shi);
            l[i] += p;
            u64 pp = dup2(p);
            acc2[i][0] = ffma2(pp, v01.x, acc2[i][0]);
            acc2[i][1] = ffma2(pp, v01.y, acc2[i][1]);
            acc2[i][2] = ffma2(pp, v23.x, acc2[i][2]);
            acc2[i][3] = ffma2(pp, v23.y, acc2[i][3]);
        }
    }
#pragma unroll
    for (int i = 0; i < 4; i++) {
        int n = n0 + tid + 512*i;
        float inv = 1.0f / l[i];
        float a[8];
#pragma unroll
        for (int d = 0; d < 4; d++) unpack2(acc2[i][d], a[2*d], a[2*d+1]);
        float* op = g_cat + (long)b*2*CN + (long)(h*HD)*NN + n;
#pragma unroll
        for (int d = 0; d < 8; d++) op[(long)d*NN] = a[d]*inv;
    }
}

// ---------------- launcher ----------------
extern "C" void kernel_launch(void* const* d_in, const int* in_sizes, int n_in,
                              void* d_out, int out_size) {
    const float* x_kv  = (const float*)d_in[0];
    const float* x_q   = (const float*)d_in[1];
    const float* w_spa = (const float*)d_in[2];
    const float* w_kv  = (const float*)d_in[3];
    const float* b_kv  = (const float*)d_in[4];
    const float* w_q   = (const float*)d_in[5];
    const float* b_q   = (const float*)d_in[6];
    const float* w_proj= (const float*)d_in[7];
    const float* b_proj= (const float*)d_in[8];
    const float* w_dw  = (const float*)d_in[9];
    const float* b_dw  = (const float*)d_in[10];
    const float* w_pw  = (const float*)d_in[11];
    const float* b_pw  = (const float*)d_in[12];
    float* out = (float*)d_out;

    float *q, *kvg, *vvol, *cat, *wcat, *bcat;
    int *idx;
    cudaGetSymbolAddress((void**)&q,    g_q);
    cudaGetSymbolAddress((void**)&kvg,  g_kvg);
    cudaGetSymbolAddress((void**)&vvol, g_vvol);
    cudaGetSymbolAddress((void**)&cat,  g_cat);
    cudaGetSymbolAddress((void**)&wcat, g_wcat);
    cudaGetSymbolAddress((void**)&bcat, g_bcat);
    cudaGetSymbolAddress((void**)&idx,  g_idx);

    // scoring path
    k_reduce<<<dim3(64, 2), 256>>>(x_kv);
    k_spa<<<32, 256>>>(w_spa);

    // mega: topk (blocks 0-1) + Q/V/KV gemms (2-289) + wcat prep (290-417)
    GemmOp opQ  = { x_q, 1L, (long)NN, (long)CN, nullptr, 0L,
                    w_q, 256, 0L, b_q, nullptr, nullptr,
                    q, (long)CC, 1L, (long)CN, CC, 2, 32 };
    GemmOp opV  = { x_kv, 1L, (long)NN, (long)CN, nullptr, 0L,
                    w_kv + CC, 512, 0L, b_kv + CC, nullptr, nullptr,
                    vvol, 1L, (long)NN, (long)CN, CC, 2, 32 };
    GemmOp opKV = { x_kv, 1L, (long)NN, (long)CN, idx, (long)KTOP,
                    w_kv, 512, 0L, b_kv, nullptr, nullptr,
                    kvg, 512L, 1L, (long)(KTOP*512), CC, 4, 4 };
    k_mega<<<2 + 288 + 128, 256>>>(opQ, opV, opKV, w_proj, w_pw, b_proj, b_pw);

    // residual conv branch -> g_cat rows 256..511 (high-occupancy 256-thread)
    k_dwconv<<<BATCH*CC*NN/4/256, 256>>>(w_dw, b_dw);

    // attention (128 CTAs = one full wave), writes g_cat rows 0..255
    k_attn<<<dim3(2, 32, 2), 512>>>();

    // fused proj+pw GEMM (K=512): out[b][c][n] = wcat^T @ g_cat + bcat
    GemmOp opF  = { wcat, 1L, 256L, 0L, nullptr, 0L,
                    cat, 4096, (long)(2*CN), nullptr, bcat, nullptr,
                    out, 4096L, 1L, (long)CN, 512, 32, 2 };
    k_sgemm<<<128, 256>>>(opF);
}

// round 17
// speedup vs baseline: 1.0548x; 1.0301x over previous
#include <cuda_runtime.h>
#include <math.h>

#define BATCH 2
#define CC 256
#define NN 4096
#define HEADS 32
#define HD 8
#define KTOP 512
#define CN (CC*NN)

typedef unsigned long long u64;

// ---- packed f32x2 helpers ----
__device__ __forceinline__ u64 pack2(float lo, float hi) {
    u64 r; asm("mov.b64 %0, {%1, %2};" : "=l"(r) : "f"(lo), "f"(hi)); return r;
}
__device__ __forceinline__ u64 dup2(float a) {
    u64 r; asm("mov.b64 %0, {%1, %1};" : "=l"(r) : "f"(a)); return r;
}
__device__ __forceinline__ void unpack2(u64 p, float& lo, float& hi) {
    asm("mov.b64 {%0, %1}, %2;" : "=f"(lo), "=f"(hi) : "l"(p));
}
__device__ __forceinline__ u64 ffma2(u64 a, u64 b, u64 c) {
    u64 d; asm("fma.rn.f32x2 %0, %1, %2, %3;" : "=l"(d) : "l"(a), "l"(b), "l"(c)); return d;
}
__device__ __forceinline__ u64 mul2(u64 a, u64 b) {
    u64 d; asm("mul.rn.f32x2 %0, %1, %2;" : "=l"(d) : "l"(a), "l"(b)); return d;
}
__device__ __forceinline__ float ex2f(float x) {
    float r; asm("ex2.approx.f32 %0, %1;" : "=f"(r) : "f"(x)); return r;
}

// ---------------- scratch (device globals; no allocation) ----------------
__device__ float g_avgmax[BATCH*2*NN];
__device__ float g_scores[BATCH*NN];
__device__ int   g_idx[BATCH*KTOP];
__device__ int   g_rcnt;                   // reduce blocks done (monotone)
__device__ int   g_scnt;                   // spa blocks done (monotone)
__device__ int   g_tflag[BATCH];           // topk done (sticky)
__device__ float g_q[BATCH*NN*CC];
__device__ float g_kvg[BATCH*KTOP*2*CC];   // [b][k][0:256]=K, [256:512]=V
__device__ float g_vvol[BATCH*CN];
__device__ float g_cat[BATCH*2*CN];        // [b][0:256]=attn_t, [256:512]=dw  (C,N)
__device__ float g_wcat[2*CC*CC];          // [k][c]: k<256 w_proj, k>=256 w_pw^T
__device__ float g_bcat[CC];               // b_proj + b_pw

// ---------------- GemmOp ----------------
struct GemmOp {
    const float* A; long a_ms, a_ks, a_bs;
    const int* rowidx; long ridx_bs;
    const float* Bw; int ldb; long w_bs;
    const float* bias_j; const float* bias_m; const float* addend;
    float* C; long c_ms, c_js, c_bs;
    int K; int tx; int ty;
};

// ---------------- reduce role: 32 blocks, float4, 256 n/block ---------------
__device__ void reduce_role(int r, const float* __restrict__ x, char* sraw) {
    float4* ssum = (float4*)sraw;            // [4][64]
    float4* smax = (float4*)(sraw + 4096);   // [4][64]
    int tid = threadIdx.x;
    int b = r >> 4, n0 = (r & 15) << 8;
    int cq = tid >> 6, t64 = tid & 63;
    const float* p = x + (long)b*CN + n0 + t64*4;
    float4 s = make_float4(0,0,0,0);
    float4 mx = make_float4(-INFINITY,-INFINITY,-INFINITY,-INFINITY);
#pragma unroll 4
    for (int c = cq*64; c < cq*64 + 64; c++) {
        float4 v = *(const float4*)(p + (long)c*NN);
        s.x += v.x; s.y += v.y; s.z += v.z; s.w += v.w;
        mx.x = fmaxf(mx.x, v.x); mx.y = fmaxf(mx.y, v.y);
        mx.z = fmaxf(mx.z, v.z); mx.w = fmaxf(mx.w, v.w);
    }
    ssum[cq*64 + t64] = s; smax[cq*64 + t64] = mx;
    __syncthreads();
    if (cq == 0) {
        float4 s0 = ssum[t64], s1 = ssum[64+t64], s2 = ssum[128+t64], s3 = ssum[192+t64];
        float4 m0 = smax[t64], m1 = smax[64+t64], m2 = smax[128+t64], m3 = smax[192+t64];
        float4 sa = make_float4((s0.x+s1.x+s2.x+s3.x)*(1.0f/CC),
                                (s0.y+s1.y+s2.y+s3.y)*(1.0f/CC),
                                (s0.z+s1.z+s2.z+s3.z)*(1.0f/CC),
                                (s0.w+s1.w+s2.w+s3.w)*(1.0f/CC));
        float4 ma = make_float4(fmaxf(fmaxf(m0.x,m1.x),fmaxf(m2.x,m3.x)),
                                fmaxf(fmaxf(m0.y,m1.y),fmaxf(m2.y,m3.y)),
                                fmaxf(fmaxf(m0.z,m1.z),fmaxf(m2.z,m3.z)),
                                fmaxf(fmaxf(m0.w,m1.w),fmaxf(m2.w,m3.w)));
        *(float4*)&g_avgmax[(b*2+0)*NN + n0 + t64*4] = sa;
        *(float4*)&g_avgmax[(b*2+1)*NN + n0 + t64*4] = ma;
    }
    __threadfence();
    __syncthreads();
    if (tid == 0) atomicAdd(&g_rcnt, 1);
}

// ---------------- spa role: 32 blocks; waits on reduce ----------------------
__device__ void spa_role(int r, const float* __restrict__ w_spa, char* sraw) {
    float* w = (float*)sraw;   // 686 floats
    int tid = threadIdx.x;
    if (tid == 0) { while (atomicAdd(&g_rcnt, 0) < 32) {} }
    __syncthreads();
    for (int l = tid; l < 686; l += 256) w[l] = w_spa[l];
    __syncthreads();
    int i = r * 256 + tid;
    int b = i >> 12, n = i & (NN-1);
    int z = n >> 8, y = (n >> 4) & 15, x0 = n & 15;
    float s = 0.f;
    for (int ci = 0; ci < 2; ci++) {
        const float* in = g_avgmax + (b*2+ci)*NN;
        const float* wc = w + ci*343;
        for (int dz = 0; dz < 7; dz++) {
            int zz = z + dz - 3; if (zz < 0 || zz > 15) continue;
            for (int dy = 0; dy < 7; dy++) {
                int yy = y + dy - 3; if (yy < 0 || yy > 15) continue;
                const float* row = in + zz*256 + yy*16;
                const float* wr = wc + dz*49 + dy*7;
                for (int dx = 0; dx < 7; dx++) {
                    int xx = x0 + dx - 3; if (xx < 0 || xx > 15) continue;
                    s += wr[dx] * row[xx];
                }
            }
        }
    }
    g_scores[i] = 1.0f / (1.0f + __expf(-s));
    __threadfence();
    __syncthreads();
    if (tid == 0) atomicAdd(&g_scnt, 1);
}

// ---------------- topk role (256 threads): waits on spa ---------------------
__device__ void topk_role(int b, char* sraw) {
    unsigned* skey = (unsigned*)sraw;                   // 16384 B
    unsigned* hist = (unsigned*)(sraw + 16384);         // 1024 B
    unsigned* scan = (unsigned*)(sraw + 17408);         // 1024 B
    unsigned* S    = (unsigned*)(sraw + 18432);         // sel,need,neednxt,cnt,tie
    int tid = threadIdx.x;
    if (tid == 0) { while (atomicAdd(&g_scnt, 0) < 32) {} }
    __syncthreads();
    const unsigned* keys = (const unsigned*)g_scores + b*NN;
    for (int i = tid; i < NN; i += 256) skey[i] = keys[i];
    if (tid == 0) S[1] = KTOP;
    __syncthreads();
    unsigned prefix = 0, pmask = 0;
    for (int shift = 24; shift >= 0; shift -= 8) {
        hist[tid] = 0;
        __syncthreads();
        for (int i = tid; i < NN; i += 256) {
            unsigned k = skey[i];
            if ((k & pmask) == prefix) atomicAdd(&hist[(k >> shift) & 255u], 1u);
        }
        __syncthreads();
        scan[tid] = hist[255 - tid];
        __syncthreads();
#pragma unroll
        for (int off = 1; off < 256; off <<= 1) {
            unsigned add = (tid >= off) ? scan[tid - off] : 0u;
            __syncthreads();
            scan[tid] += add;
            __syncthreads();
        }
        unsigned need = S[1];
        unsigned suf = scan[tid], above = tid ? scan[tid - 1] : 0u;
        if (suf >= need && above < need) { S[0] = 255u - tid; S[2] = need - above; }
        __syncthreads();
        prefix |= S[0] << shift;
        pmask  |= 255u << shift;
        if (tid == 0) S[1] = S[2];
        __syncthreads();
    }
    if (tid == 0) { S[3] = 0; S[4] = 0; }
    __syncthreads();
    unsigned tietake = S[1];
    for (int i = tid; i < NN; i += 256) {
        unsigned k = skey[i];
        if (k > prefix) {
            unsigned p = atomicAdd(&S[3], 1u);
            g_idx[b*KTOP + p] = i;
        } else if (k == prefix) {
            unsigned t = atomicAdd(&S[4], 1u);
            if (t < tietake) {
                unsigned p = atomicAdd(&S[3], 1u);
                g_idx[b*KTOP + p] = i;
            }
        }
    }
    __threadfence();
    __syncthreads();
    if (tid == 0) atomicExch(&g_tflag[b], 1);
}

// ---------------- mega kernel: reduce+spa+topk+QVK gemms+prep ---------------
// bids: reduce 0-31 | spa 32-63 | topk 64-65 | Q 66-193 | V 194-321 |
//       KV 322-353 | prep 354-481
__global__ void __launch_bounds__(256) k_mega(
    GemmOp o1, GemmOp o2, GemmOp o3,
    const float* __restrict__ x_kv, const float* __restrict__ w_spa,
    const float* __restrict__ w_proj, const float* __restrict__ w_pw,
    const float* __restrict__ b_proj, const float* __restrict__ b_pw)
{
    __shared__ __align__(16) char sraw[34816];
    int bid = blockIdx.x;
    int tid = threadIdx.x;

    if (bid < 32)  { reduce_role(bid, x_kv, sraw); return; }
    if (bid < 64)  { spa_role(bid - 32, w_spa, sraw); return; }
    if (bid < 66)  { topk_role(bid - 64, sraw); return; }
    bid -= 66;
    if (bid >= 288) {                       // prep role: 128 blocks x 1024 elems
        int e0 = (bid - 288) * 1024 + tid * 4;
#pragma unroll
        for (int j = 0; j < 4; j++) {
            int e = e0 + j;
            int k = e >> 8, c = e & 255;
            g_wcat[e] = (k < CC) ? w_proj[k*CC + c] : w_pw[c*CC + (k - CC)];
            if (e < CC) g_bcat[e] = b_proj[e] + b_pw[e];
        }
        return;
    }

    // ---- GEMM role ----
    float (&As)[2][16][132] = *reinterpret_cast<float(*)[2][16][132]>(sraw);
    float (&Bs)[2][16][132] = *reinterpret_cast<float(*)[2][16][132]>(sraw + 16896);
    int*  sidx = (int*)(sraw + 33792);

    GemmOp op; int local;
    if (bid < 128)      { op = o1; local = bid; }
    else if (bid < 256) { op = o2; local = bid - 128; }
    else                { op = o3; local = bid - 256; }
    int per = op.tx * op.ty;
    int bz  = local / per;
    int rem = local - bz * per;
    int m0 = (rem / op.tx) * 128, j0 = (rem % op.tx) * 128;

    const float* Ab = op.A  + (long)bz * op.a_bs;
    const float* Bb = op.Bw + (long)bz * op.w_bs;

    int mode = op.rowidx ? 2 : ((op.a_ks == 1) ? 0 : 1);

    int warp = tid >> 5, lane = tid & 31;
    int tm = (warp & 3) * 32 + (lane & 3) * 8;
    int tn = (warp >> 2) * 64 + (lane >> 2) * 8;

    int am  = tid >> 1, ak = (tid & 1) * 8;     // mode 0
    int am4 = (tid & 31) * 4, ak2 = tid >> 5;   // mode 1
    int bj4 = (tid & 31) * 4, bk  = tid >> 5;   // B

    long goff[8]; int gmm[8], gkk[8];
    if (mode == 2) {
        // wait for topk blocks (strictly lower bids) to publish g_idx
        if (tid == 0) { while (atomicAdd(&g_tflag[bz], 0) == 0) {} }
        __syncthreads();
        if (tid < 128) sidx[tid] = op.rowidx[(long)bz * op.ridx_bs + m0 + tid];
        __syncthreads();
#pragma unroll
        for (int r = 0; r < 8; r++) {
            int l = tid + r * 256;
            gmm[r] = l & 127; gkk[r] = l >> 7;
            goff[r] = (long)gkk[r] * op.a_ks + sidx[gmm[r]];
        }
    }

    const float* pA = Ab;
    if (mode == 0)      pA = Ab + (long)(m0 + am) * op.a_ms + ak;
    else if (mode == 1) pA = Ab + (long)ak2 * op.a_ks + m0 + am4;
    const float* pB = Bb + (long)bk * op.ldb + j0 + bj4;

    float fa[8]; float4 fb0, fb1;
    auto fetch = [&](int t) {
        long k0 = (long)t * 16;
        if (mode == 0) {
            float4 v0 = *(const float4*)(pA + k0);
            float4 v1 = *(const float4*)(pA + k0 + 4);
            fa[0]=v0.x; fa[1]=v0.y; fa[2]=v0.z; fa[3]=v0.w;
            fa[4]=v1.x; fa[5]=v1.y; fa[6]=v1.z; fa[7]=v1.w;
        } else if (mode == 1) {
            float4 v0 = *(const float4*)(pA + k0 * op.a_ks);
            float4 v1 = *(const float4*)(pA + (k0 + 8) * op.a_ks);
            fa[0]=v0.x; fa[1]=v0.y; fa[2]=v0.z; fa[3]=v0.w;
            fa[4]=v1.x; fa[5]=v1.y; fa[6]=v1.z; fa[7]=v1.w;
        } else {
#pragma unroll
            for (int r = 0; r < 8; r++) fa[r] = Ab[k0 * op.a_ks + goff[r]];
        }
        fb0 = *(const float4*)(pB + k0 * op.ldb);
        fb1 = *(const float4*)(pB + (k0 + 8) * op.ldb);
    };
    auto stos = [&](int bs) {
        if (mode == 0) {
#pragma unroll
            for (int t = 0; t < 8; t++) As[bs][ak+t][am] = fa[t];
        } else if (mode == 1) {
            *(float4*)&As[bs][ak2][am4]   = make_float4(fa[0],fa[1],fa[2],fa[3]);
            *(float4*)&As[bs][ak2+8][am4] = make_float4(fa[4],fa[5],fa[6],fa[7]);
        } else {
#pragma unroll
            for (int r = 0; r < 8; r++) As[bs][gkk[r]][gmm[r]] = fa[r];
        }
        *(float4*)&Bs[bs][bk][bj4]   = fb0;
        *(float4*)&Bs[bs][bk+8][bj4] = fb1;
    };

    u64 acc2[8][4] = {};
    fetch(0); stos(0);
    __syncthreads();

    int nk = op.K >> 4, buf = 0;
    for (int t = 0; t < nk; t++) {
        bool more = (t + 1 < nk);
        if (more) fetch(t + 1);
#pragma unroll
        for (int kk = 0; kk < 16; kk++) {
            float av[8];
            *(float4*)(av)   = *(const float4*)&As[buf][kk][tm];
            *(float4*)(av+4) = *(const float4*)&As[buf][kk][tm+4];
            ulonglong2 b01 = *(const ulonglong2*)&Bs[buf][kk][tn];
            ulonglong2 b23 = *(const ulonglong2*)&Bs[buf][kk][tn+4];
            u64 bv[4] = {b01.x, b01.y, b23.x, b23.y};
#pragma unroll
            for (int i = 0; i < 8; i++) {
                u64 ad = dup2(av[i]);
#pragma unroll
                for (int j = 0; j < 4; j++)
                    acc2[i][j] = ffma2(ad, bv[j], acc2[i][j]);
            }
        }
        if (more) { stos(buf ^ 1); __syncthreads(); buf ^= 1; }
    }

    float acc[8][8];
#pragma unroll
    for (int i = 0; i < 8; i++)
#pragma unroll
        for (int j = 0; j < 4; j++)
            unpack2(acc2[i][j], acc[i][2*j], acc[i][2*j+1]);

    float bj[8], bm[8];
#pragma unroll
    for (int j = 0; j < 8; j++) bj[j] = op.bias_j ? op.bias_j[j0+tn+j] : 0.f;
#pragma unroll
    for (int i = 0; i < 8; i++) bm[i] = op.bias_m ? op.bias_m[m0+tm+i] : 0.f;
    long cb = (long)bz * op.c_bs;
    if (op.c_js == 1) {
#pragma unroll
        for (int i = 0; i < 8; i++) {
            long off = cb + (long)(m0+tm+i)*op.c_ms + (j0+tn);
            float4 v0 = make_float4(acc[i][0]+bj[0]+bm[i], acc[i][1]+bj[1]+bm[i],
                                    acc[i][2]+bj[2]+bm[i], acc[i][3]+bj[3]+bm[i]);
            float4 v1 = make_float4(acc[i][4]+bj[4]+bm[i], acc[i][5]+bj[5]+bm[i],
                                    acc[i][6]+bj[6]+bm[i], acc[i][7]+bj[7]+bm[i]);
            if (op.addend) {
                float4 a0 = *(const float4*)&op.addend[off];
                float4 a1 = *(const float4*)&op.addend[off+4];
                v0.x+=a0.x; v0.y+=a0.y; v0.z+=a0.z; v0.w+=a0.w;
                v1.x+=a1.x; v1.y+=a1.y; v1.z+=a1.z; v1.w+=a1.w;
            }
            *(float4*)&op.C[off]   = v0;
            *(float4*)&op.C[off+4] = v1;
        }
    } else {
#pragma unroll
        for (int i = 0; i < 8; i++)
#pragma unroll
            for (int j = 0; j < 8; j++) {
                long off = cb + (long)(m0+tm+i)*op.c_ms + (long)(j0+tn+j)*op.c_js;
                float v = acc[i][j] + bj[j] + bm[i];
                if (op.addend) v += op.addend[off];
                op.C[off] = v;
            }
    }
}

// ---------------- plain SGEMM kernel (final fused proj+pw) -------------------
__global__ void __launch_bounds__(256) k_sgemm(GemmOp op) {
    __shared__ float As[2][16][132];
    __shared__ float Bs[2][16][132];
    int bid = blockIdx.x;
    int per = op.tx * op.ty;
    int bz  = bid / per;
    int rem = bid - bz * per;
    int m0 = (rem / op.tx) * 128, j0 = (rem % op.tx) * 128;
    int tid = threadIdx.x;
    const float* Ab = op.A  + (long)bz * op.a_bs;
    const float* Bb = op.Bw + (long)bz * op.w_bs;
    int mode = (op.a_ks == 1) ? 0 : 1;

    int warp = tid >> 5, lane = tid & 31;
    int tm = (warp & 3) * 32 + (lane & 3) * 8;
    int tn = (warp >> 2) * 64 + (lane >> 2) * 8;
    int am  = tid >> 1, ak = (tid & 1) * 8;
    int am4 = (tid & 31) * 4, ak2 = tid >> 5;
    int bj4 = (tid & 31) * 4, bk  = tid >> 5;

    const float* pA = (mode == 0) ? (Ab + (long)(m0 + am) * op.a_ms + ak)
                                  : (Ab + (long)ak2 * op.a_ks + m0 + am4);
    const float* pB = Bb + (long)bk * op.ldb + j0 + bj4;

    float fa[8]; float4 fb0, fb1;
    auto fetch = [&](int t) {
        long k0 = (long)t * 16;
        if (mode == 0) {
            float4 v0 = *(const float4*)(pA + k0);
            float4 v1 = *(const float4*)(pA + k0 + 4);
            fa[0]=v0.x; fa[1]=v0.y; fa[2]=v0.z; fa[3]=v0.w;
            fa[4]=v1.x; fa[5]=v1.y; fa[6]=v1.z; fa[7]=v1.w;
        } else {
            float4 v0 = *(const float4*)(pA + k0 * op.a_ks);
            float4 v1 = *(const float4*)(pA + (k0 + 8) * op.a_ks);
            fa[0]=v0.x; fa[1]=v0.y; fa[2]=v0.z; fa[3]=v0.w;
            fa[4]=v1.x; fa[5]=v1.y; fa[6]=v1.z; fa[7]=v1.w;
        }
        fb0 = *(const float4*)(pB + k0 * op.ldb);
        fb1 = *(const float4*)(pB + (k0 + 8) * op.ldb);
    };
    auto stos = [&](int bs) {
        if (mode == 0) {
#pragma unroll
            for (int t = 0; t < 8; t++) As[bs][ak+t][am] = fa[t];
        } else {
            *(float4*)&As[bs][ak2][am4]   = make_float4(fa[0],fa[1],fa[2],fa[3]);
            *(float4*)&As[bs][ak2+8][am4] = make_float4(fa[4],fa[5],fa[6],fa[7]);
        }
        *(float4*)&Bs[bs][bk][bj4]   = fb0;
        *(float4*)&Bs[bs][bk+8][bj4] = fb1;
    };

    u64 acc2[8][4] = {};
    fetch(0); stos(0);
    __syncthreads();
    int nk = op.K >> 4, buf = 0;
    for (int t = 0; t < nk; t++) {
        bool more = (t + 1 < nk);
        if (more) fetch(t + 1);
#pragma unroll
        for (int kk = 0; kk < 16; kk++) {
            float av[8];
            *(float4*)(av)   = *(const float4*)&As[buf][kk][tm];
            *(float4*)(av+4) = *(const float4*)&As[buf][kk][tm+4];
            ulonglong2 b01 = *(const ulonglong2*)&Bs[buf][kk][tn];
            ulonglong2 b23 = *(const ulonglong2*)&Bs[buf][kk][tn+4];
            u64 bv[4] = {b01.x, b01.y, b23.x, b23.y};
#pragma unroll
            for (int i = 0; i < 8; i++) {
                u64 ad = dup2(av[i]);
#pragma unroll
                for (int j = 0; j < 4; j++)
                    acc2[i][j] = ffma2(ad, bv[j], acc2[i][j]);
            }
        }
        if (more) { stos(buf ^ 1); __syncthreads(); buf ^= 1; }
    }
    float acc[8][8];
#pragma unroll
    for (int i = 0; i < 8; i++)
#pragma unroll
        for (int j = 0; j < 4; j++)
            unpack2(acc2[i][j], acc[i][2*j], acc[i][2*j+1]);
    float bj[8], bm[8];
#pragma unroll
    for (int j = 0; j < 8; j++) bj[j] = op.bias_j ? op.bias_j[j0+tn+j] : 0.f;
#pragma unroll
    for (int i = 0; i < 8; i++) bm[i] = op.bias_m ? op.bias_m[m0+tm+i] : 0.f;
    long cb = (long)bz * op.c_bs;
#pragma unroll
    for (int i = 0; i < 8; i++) {
        long off = cb + (long)(m0+tm+i)*op.c_ms + (j0+tn);
        float4 v0 = make_float4(acc[i][0]+bj[0]+bm[i], acc[i][1]+bj[1]+bm[i],
                                acc[i][2]+bj[2]+bm[i], acc[i][3]+bj[3]+bm[i]);
        float4 v1 = make_float4(acc[i][4]+bj[4]+bm[i], acc[i][5]+bj[5]+bm[i],
                                acc[i][6]+bj[6]+bm[i], acc[i][7]+bj[7]+bm[i]);
        if (op.addend) {
            float4 a0 = *(const float4*)&op.addend[off];
            float4 a1 = *(const float4*)&op.addend[off+4];
            v0.x+=a0.x; v0.y+=a0.y; v0.z+=a0.z; v0.w+=a0.w;
            v1.x+=a1.x; v1.y+=a1.y; v1.z+=a1.z; v1.w+=a1.w;
        }
        *(float4*)&op.C[off]   = v0;
        *(float4*)&op.C[off+4] = v1;
    }
}

// ---------------- depthwise 3x3x3 conv (256 thr, high occupancy) -------------
__global__ void k_dwconv(const float* __restrict__ w_dw, const float* __restrict__ b_dw) {
    int i = blockIdx.x * blockDim.x + threadIdx.x;   // BATCH*CC*16*16*4
    int xq = i & 3, y = (i >> 2) & 15, z = (i >> 6) & 15, c = (i >> 10) & 255, b = i >> 18;
    const float* base = g_vvol + ((long)b*CC + c)*NN;
    float w27[27];
#pragma unroll
    for (int t = 0; t < 27; t++) w27[t] = w_dw[c*27 + t];
    float bias = b_dw[c];
    float o0 = bias, o1 = bias, o2 = bias, o3 = bias;
    int x0 = xq * 4;
#pragma unroll
    for (int dz = 0; dz < 3; dz++) {
        int zz = z + dz - 1; if (zz < 0 || zz > 15) continue;
#pragma unroll
        for (int dy = 0; dy < 3; dy++) {
            int yy = y + dy - 1; if (yy < 0 || yy > 15) continue;
            const float* r = base + zz*256 + yy*16 + x0;
            float4 m4 = *(const float4*)r;
            float xl = (xq > 0) ? r[-1] : 0.f;
            float xr = (xq < 3) ? r[4]  : 0.f;
            float wl = w27[dz*9+dy*3], wm = w27[dz*9+dy*3+1], wr = w27[dz*9+dy*3+2];
            o0 += wl*xl   + wm*m4.x + wr*m4.y;
            o1 += wl*m4.x + wm*m4.y + wr*m4.z;
            o2 += wl*m4.y + wm*m4.z + wr*m4.w;
            o3 += wl*m4.z + wm*m4.w + wr*xr;
        }
    }
    *(float4*)&g_cat[((long)b*512 + 256 + c)*NN + z*256 + y*16 + x0]
        = make_float4(o0,o1,o2,o3);
}

// ---------------- attention: FFMA2 + ex2; writes g_cat rows 0..255 -----------
__global__ void __launch_bounds__(512) k_attn() {
    __shared__ float Ks[KTOP*HD];   // 16 KB
    __shared__ float Vs[KTOP*HD];   // 16 KB
    int b = blockIdx.z, h = blockIdx.y, nt = blockIdx.x;
    int tid = threadIdx.x;
    const float* kgb = g_kvg + (long)b*KTOP*512 + h*HD;        // K at col h*8
    const float* vgb = kgb + CC;                               // V at col 256+h*8
    {
        int k = tid;   // 512 threads, 512 rows
        *(float4*)(Ks + k*8)     = *(const float4*)(kgb + (long)k*512);
        *(float4*)(Ks + k*8 + 4) = *(const float4*)(kgb + (long)k*512 + 4);
        *(float4*)(Vs + k*8)     = *(const float4*)(vgb + (long)k*512);
        *(float4*)(Vs + k*8 + 4) = *(const float4*)(vgb + (long)k*512 + 4);
    }
    __syncthreads();
    const float cs = 0.35355339059327373f * 1.4426950408889634f; // scale*log2e
    u64 qr2[4][4], acc2[4][4] = {};
    float l[4] = {0,0,0,0};
    int n0 = nt * 2048;
#pragma unroll
    for (int i = 0; i < 4; i++) {
        int n = n0 + tid + 512*i;
        const float* qp = g_q + ((long)b*NN + n)*CC + h*HD;
        float4 qa = *(const float4*)qp;
        float4 qb = *(const float4*)(qp + 4);
        qr2[i][0] = pack2(qa.x*cs, qa.y*cs);
        qr2[i][1] = pack2(qa.z*cs, qa.w*cs);
        qr2[i][2] = pack2(qb.x*cs, qb.y*cs);
        qr2[i][3] = pack2(qb.z*cs, qb.w*cs);
    }
#pragma unroll 2
    for (int k = 0; k < KTOP; k++) {
        ulonglong2 k01 = *(const ulonglong2*)(Ks + k*8);
        ulonglong2 k23 = *(const ulonglong2*)(Ks + k*8 + 4);
        ulonglong2 v01 = *(const ulonglong2*)(Vs + k*8);
        ulonglong2 v23 = *(const ulonglong2*)(Vs + k*8 + 4);
#pragma unroll
        for (int i = 0; i < 4; i++) {
            u64 t2 = mul2(qr2[i][0], k01.x);
            t2 = ffma2(qr2[i][1], k01.y, t2);
            t2 = ffma2(qr2[i][2], k23.x, t2);
            t2 = ffma2(qr2[i][3], k23.y, t2);
            float slo, shi; unpack2(t2, slo, shi);
            float p = ex2f(slo + shi);
            l[i] += p;
            u64 pp = dup2(p);
            acc2[i][0] = ffma2(pp, v01.x, acc2[i][0]);
            acc2[i][1] = ffma2(pp, v01.y, acc2[i][1]);
            acc2[i][2] = ffma2(pp, v23.x, acc2[i][2]);
            acc2[i][3] = ffma2(pp, v23.y, acc2[i][3]);
        }
    }
#pragma unroll
    for (int i = 0; i < 4; i++) {
        int n = n0 + tid + 512*i;
        float inv = 1.0f / l[i];
        float a[8];
#pragma unroll
        for (int d = 0; d < 4; d++) unpack2(acc2[i][d], a[2*d], a[2*d+1]);
        float* op = g_cat + (long)b*2*CN + (long)(h*HD)*NN + n;
#pragma unroll
        for (int d = 0; d < 8; d++) op[(long)d*NN] = a[d]*inv;
    }
}

// ---------------- launcher ----------------
extern "C" void kernel_launch(void* const* d_in, const int* in_sizes, int n_in,
                              void* d_out, int out_size) {
    const float* x_kv  = (const float*)d_in[0];
    const float* x_q   = (const float*)d_in[1];
    const float* w_spa = (const float*)d_in[2];
    const float* w_kv  = (const float*)d_in[3];
    const float* b_kv  = (const float*)d_in[4];
    const float* w_q   = (const float*)d_in[5];
    const float* b_q   = (const float*)d_in[6];
    const float* w_proj= (const float*)d_in[7];
    const float* b_proj= (const float*)d_in[8];
    const float* w_dw  = (const float*)d_in[9];
    const float* b_dw  = (const float*)d_in[10];
    const float* w_pw  = (const float*)d_in[11];
    const float* b_pw  = (const float*)d_in[12];
    float* out = (float*)d_out;

    float *q, *kvg, *vvol, *cat, *wcat, *bcat;
    int *idx;
    cudaGetSymbolAddress((void**)&q,    g_q);
    cudaGetSymbolAddress((void**)&kvg,  g_kvg);
    cudaGetSymbolAddress((void**)&vvol, g_vvol);
    cudaGetSymbolAddress((void**)&cat,  g_cat);
    cudaGetSymbolAddress((void**)&wcat, g_wcat);
    cudaGetSymbolAddress((void**)&bcat, g_bcat);
    cudaGetSymbolAddress((void**)&idx,  g_idx);

    // mega: reduce(0-31) + spa(32-63) + topk(64-65) + Q/V/KV gemms + prep
    GemmOp opQ  = { x_q, 1L, (long)NN, (long)CN, nullptr, 0L,
                    w_q, 256, 0L, b_q, nullptr, nullptr,
                    q, (long)CC, 1L, (long)CN, CC, 2, 32 };
    GemmOp opV  = { x_kv, 1L, (long)NN, (long)CN, nullptr, 0L,
                    w_kv + CC, 512, 0L, b_kv + CC, nullptr, nullptr,
                    vvol, 1L, (long)NN, (long)CN, CC, 2, 32 };
    GemmOp opKV = { x_kv, 1L, (long)NN, (long)CN, idx, (long)KTOP,
                    w_kv, 512, 0L, b_kv, nullptr, nullptr,
                    kvg, 512L, 1L, (long)(KTOP*512), CC, 4, 4 };
    k_mega<<<66 + 288 + 128, 256>>>(opQ, opV, opKV, x_kv, w_spa,
                                    w_proj, w_pw, b_proj, b_pw);

    // residual conv branch -> g_cat rows 256..511 (high-occupancy 256-thread)
    k_dwconv<<<BATCH*CC*NN/4/256, 256>>>(w_dw, b_dw);

    // attention (128 CTAs = one full wave), writes g_cat rows 0..255
    k_attn<<<dim3(2, 32, 2), 512>>>();

    // fused proj+pw GEMM (K=512): out[b][c][n] = wcat^T @ g_cat + bcat
    GemmOp opF  = { wcat, 1L, 256L, 0L, nullptr, 0L,
                    cat, 4096, (long)(2*CN), nullptr, bcat, nullptr,
                    out, 4096L, 1L, (long)CN, 512, 32, 2 };
    k_sgemm<<<128, 256>>>(opF);
}